// round 7
// baseline (speedup 1.0000x reference)
#include <cuda_runtime.h>

// ---------------------------------------------------------------------------
// SAMMCodebook.encode on GB300 (sm_103a) — fp32 compute, FLOAT32 output.
//   h: [N=65536, D=1024] f32, codebook: [K=512, D=1024] f32 -> out [N]
//   argmin_k ||h_n - c_k||^2 == argmax_k ( <h_n,c_k> - 0.5*||c_k||^2 )
//
// RESUBMISSION of R5 (container infra failed twice; hypothesis untested):
// the harness's __output__ dtype is float32 — int32 index bit-patterns read
// as fp32 denormals, pinning rel_err at exactly 1.0 across four rounds.
// Indices (< 512) are exactly representable in fp32; emit them as floats.
//
// One CTA (256 thr) = 64 rows x all 512 codewords; D streamed in 16-chunks
// through SMEM. Thread tile 8 rows x 16 cols, scalar FFMA accumulators,
// ||c||^2 accumulated inline per-thread (each thread owns 16 fixed columns).
// ---------------------------------------------------------------------------

constexpr int BM  = 64;            // rows per CTA
constexpr int BD  = 16;            // D-chunk
constexpr int KCB = 512;           // codewords, all in one CTA
constexpr int CSS = KCB + 4;       // 516: keeps float4 rows 16B-aligned
constexpr int HSS = BM + 4;        // 68

__global__ __launch_bounds__(256)
void encode_kernel(const float* __restrict__ h, const float* __restrict__ cb,
                   float* __restrict__ out, int N, int D) {
    __shared__ float c_s[BD * CSS];   // c_s[d][k]  (d-major, transposed)
    __shared__ float h_s[BD * HSS];   // h_s[d][r]

    const int tid  = threadIdx.x;
    const int tx   = tid & 31;         // lane: cols {g*128 + 4*tx + j}
    const int ty   = tid >> 5;         // warp: rows ty*8 .. ty*8+7
    const int base = blockIdx.x * BM;

    // Diagnostic sentinel — unconditionally overwritten by the epilogue.
    // If a future run shows astronomically large rel_err, the epilogue died.
    if (tid < BM) out[base + tid] = 2.0e9f;

    float acc[8][16];
    float csq[16];
    #pragma unroll
    for (int c = 0; c < 16; c++) csq[c] = 0.f;
    #pragma unroll
    for (int i = 0; i < 8; i++)
        #pragma unroll
        for (int c = 0; c < 16; c++) acc[i][c] = 0.f;

    // global->smem mapping: 256 threads, coalesced along D
    const int lr  = tid >> 2;          // 0..63
    const int ld4 = tid & 3;           // 0..3

    for (int d0 = 0; d0 < D; d0 += BD) {
        // stage next chunk in registers while previous compute drains
        float4 hv = *reinterpret_cast<const float4*>(
            h + (size_t)(base + lr) * (size_t)D + d0 + 4 * ld4);
        float4 cv[8];
        #pragma unroll
        for (int i = 0; i < 8; i++)
            cv[i] = *reinterpret_cast<const float4*>(
                cb + (size_t)(lr + 64 * i) * (size_t)D + d0 + 4 * ld4);

        __syncthreads();               // previous chunk fully consumed

        #pragma unroll
        for (int j = 0; j < 4; j++)
            h_s[(4 * ld4 + j) * HSS + lr] = (&hv.x)[j];
        #pragma unroll
        for (int i = 0; i < 8; i++)
            #pragma unroll
            for (int j = 0; j < 4; j++)
                c_s[(4 * ld4 + j) * CSS + lr + 64 * i] = (&cv[i].x)[j];

        __syncthreads();

        #pragma unroll 8
        for (int d = 0; d < BD; ++d) {
            float a[8];
            const float* hd = h_s + d * HSS + 8 * ty;
            #pragma unroll
            for (int i = 0; i < 8; i++) a[i] = hd[i];       // warp-broadcast

            float4 b[4];
            const float* cd = c_s + d * CSS + 4 * tx;
            #pragma unroll
            for (int g = 0; g < 4; g++)                      // LDS.128, 16B-aligned
                b[g] = *reinterpret_cast<const float4*>(cd + g * 128);

            // inline ||c||^2 for this thread's 16 fixed columns
            #pragma unroll
            for (int g = 0; g < 4; g++) {
                csq[4 * g + 0] = fmaf(b[g].x, b[g].x, csq[4 * g + 0]);
                csq[4 * g + 1] = fmaf(b[g].y, b[g].y, csq[4 * g + 1]);
                csq[4 * g + 2] = fmaf(b[g].z, b[g].z, csq[4 * g + 2]);
                csq[4 * g + 3] = fmaf(b[g].w, b[g].w, csq[4 * g + 3]);
            }

            #pragma unroll
            for (int i = 0; i < 8; i++)
                #pragma unroll
                for (int g = 0; g < 4; g++) {
                    acc[i][4 * g + 0] = fmaf(a[i], b[g].x, acc[i][4 * g + 0]);
                    acc[i][4 * g + 1] = fmaf(a[i], b[g].y, acc[i][4 * g + 1]);
                    acc[i][4 * g + 2] = fmaf(a[i], b[g].z, acc[i][4 * g + 2]);
                    acc[i][4 * g + 3] = fmaf(a[i], b[g].w, acc[i][4 * g + 3]);
                }
        }
    }

    // ---- epilogue: score = dot - 0.5*||c||^2, per-row argmax over 512 ----
    #pragma unroll
    for (int c = 0; c < 16; c++) csq[c] *= 0.5f;

    #pragma unroll
    for (int i = 0; i < 8; i++) {
        float bestv = -3.402823466e+38f;
        int   besti = 0x7fffffff;
        #pragma unroll
        for (int c = 0; c < 16; c++) {
            int col = (c >> 2) * 128 + 4 * tx + (c & 3);
            float v = acc[i][c] - csq[c];
            if (v > bestv || (v == bestv && col < besti)) { bestv = v; besti = col; }
        }
        #pragma unroll
        for (int o = 16; o; o >>= 1) {   // butterfly: max value, min index on tie
            float ov = __shfl_xor_sync(0xffffffffu, bestv, o);
            int   oi = __shfl_xor_sync(0xffffffffu, besti, o);
            if (ov > bestv || (ov == bestv && oi < besti)) { bestv = ov; besti = oi; }
        }
        if (tx == 0) out[base + ty * 8 + i] = (float)besti;   // FLOAT output
    }
}

// ---------------------------------------------------------------------------
extern "C" void kernel_launch(void* const* d_in, const int* in_sizes, int n_in,
                              void* d_out, int out_size) {
    const int D = 1024;

    // Runtime input-order disambiguation: h (67.1M elems) vs codebook (0.52M).
    const float* h;
    const float* cb;
    int N;
    if (in_sizes[0] >= in_sizes[1]) {
        h  = (const float*)d_in[0];  N = in_sizes[0] / D;
        cb = (const float*)d_in[1];
    } else {
        h  = (const float*)d_in[1];  N = in_sizes[1] / D;
        cb = (const float*)d_in[0];
    }
    float* out = (float*)d_out;

    encode_kernel<<<N / BM, 256>>>(h, cb, out, N, D);
}

// round 10
// speedup vs baseline: 1.7908x; 1.7908x over previous
#include <cuda_runtime.h>

// ---------------------------------------------------------------------------
// SAMMCodebook.encode on GB300 (sm_103a) — packed fma.rn.f32x2 (FFMA2) version.
// RESUBMISSION of R8 unchanged (container infra failed twice; experiment
// never ran). Baseline to beat: R7 scalar-FFMA at 3072.7 us, fma=60%.
//
//   h: [N=65536, D=1024] f32, codebook: [K=512, D=1024] f32 -> float out [N]
//   argmin_k ||h_n - c_k||^2 == argmax_k ( <h_n,c_k> - 0.5*||c_k||^2 )
//
// FFMA2 executes 2 fp32 FMAs per fma-pipe slot -> 2x throughput ceiling.
// acc: 8 rows x 8 col-pairs of u64-packed fp32 lanes.
// b:   LDS.128 float4, reinterpreted as two u64 packs (no extra instrs).
// a:   h_s stores {v,v} duplicated so the broadcast multiplier is one LDS.64.
// ---------------------------------------------------------------------------

#define FMA2(acc, a, b) \
    asm("fma.rn.f32x2 %0, %1, %2, %0;" : "+l"(acc) : "l"(a), "l"(b))

constexpr int BM  = 64;             // rows per CTA
constexpr int BD  = 16;             // D-chunk
constexpr int KCB = 512;            // codewords, all in one CTA
constexpr int CSS = KCB + 4;        // 516 floats: float4 rows stay 16B-aligned
constexpr int HSS = 2 * BM + 8;     // 136 floats: duplicated {v,v} rows

__global__ __launch_bounds__(256)
void encode_kernel(const float* __restrict__ h, const float* __restrict__ cb,
                   float* __restrict__ out, int N, int D) {
    __shared__ float c_s[BD * CSS];   // c_s[d][k]        (d-major, transposed)
    __shared__ float h_s[BD * HSS];   // h_s[d][2r,2r+1] = {v,v}

    const int tid  = threadIdx.x;
    const int tx   = tid & 31;         // lane: col pairs {g*128 + 4*tx + 2m}
    const int ty   = tid >> 5;         // warp: rows ty*8 .. ty*8+7
    const int base = blockIdx.x * BM;

    unsigned long long acc[8][8];      // [row][colpair] — 2 fp32 lanes each
    unsigned long long csq2[8];        // packed ||c||^2 accumulators
    #pragma unroll
    for (int p = 0; p < 8; p++) csq2[p] = 0ull;
    #pragma unroll
    for (int i = 0; i < 8; i++)
        #pragma unroll
        for (int p = 0; p < 8; p++) acc[i][p] = 0ull;

    // global->smem mapping: 256 threads, coalesced along D
    const int lr  = tid >> 2;          // 0..63
    const int ld4 = tid & 3;           // 0..3

    for (int d0 = 0; d0 < D; d0 += BD) {
        // stage next chunk in registers while previous compute drains
        float4 hv = *reinterpret_cast<const float4*>(
            h + (size_t)(base + lr) * (size_t)D + d0 + 4 * ld4);
        float4 cv[8];
        #pragma unroll
        for (int i = 0; i < 8; i++)
            cv[i] = *reinterpret_cast<const float4*>(
                cb + (size_t)(lr + 64 * i) * (size_t)D + d0 + 4 * ld4);

        __syncthreads();               // previous chunk fully consumed

        #pragma unroll
        for (int j = 0; j < 4; j++) {  // duplicated store {v,v} as one STS.64
            float v = (&hv.x)[j];
            float2 vv = make_float2(v, v);
            *reinterpret_cast<float2*>(&h_s[(4 * ld4 + j) * HSS + 2 * lr]) = vv;
        }
        #pragma unroll
        for (int i = 0; i < 8; i++)
            #pragma unroll
            for (int j = 0; j < 4; j++)
                c_s[(4 * ld4 + j) * CSS + lr + 64 * i] = (&cv[i].x)[j];

        __syncthreads();

        #pragma unroll 8
        for (int d = 0; d < BD; ++d) {
            unsigned long long a2[8];
            const float* hd = h_s + d * HSS + 16 * ty;      // 2*(ty*8)
            #pragma unroll
            for (int i = 0; i < 8; i++)                      // broadcast LDS.64
                a2[i] = *reinterpret_cast<const unsigned long long*>(hd + 2 * i);

            unsigned long long b2[8];
            const float* cd = c_s + d * CSS + 4 * tx;
            #pragma unroll
            for (int g = 0; g < 4; g++) {                    // LDS.128 -> 2 packs
                float4 bq = *reinterpret_cast<const float4*>(cd + g * 128);
                b2[2 * g]     = *reinterpret_cast<unsigned long long*>(&bq.x);
                b2[2 * g + 1] = *reinterpret_cast<unsigned long long*>(&bq.z);
            }

            #pragma unroll
            for (int p = 0; p < 8; p++)                      // packed ||c||^2
                FMA2(csq2[p], b2[p], b2[p]);

            #pragma unroll
            for (int i = 0; i < 8; i++)
                #pragma unroll
                for (int p = 0; p < 8; p++)
                    FMA2(acc[i][p], a2[i], b2[p]);
        }
    }

    // ---- epilogue: score = dot - 0.5*||c||^2, per-row argmax over 512 ----
    float half_csq[16];
    #pragma unroll
    for (int p = 0; p < 8; p++) {
        half_csq[2 * p]     = 0.5f * __uint_as_float((unsigned)(csq2[p] & 0xffffffffull));
        half_csq[2 * p + 1] = 0.5f * __uint_as_float((unsigned)(csq2[p] >> 32));
    }

    #pragma unroll
    for (int i = 0; i < 8; i++) {
        float bestv = -3.402823466e+38f;
        int   besti = 0x7fffffff;
        #pragma unroll
        for (int p = 0; p < 8; p++) {
            int col = (p >> 1) * 128 + 4 * tx + (p & 1) * 2;
            float lo = __uint_as_float((unsigned)(acc[i][p] & 0xffffffffull));
            float hi = __uint_as_float((unsigned)(acc[i][p] >> 32));
            float v0 = lo - half_csq[2 * p];
            float v1 = hi - half_csq[2 * p + 1];
            if (v0 > bestv || (v0 == bestv && col < besti))       { bestv = v0; besti = col; }
            if (v1 > bestv || (v1 == bestv && (col + 1) < besti)) { bestv = v1; besti = col + 1; }
        }
        #pragma unroll
        for (int o = 16; o; o >>= 1) {   // butterfly: max value, min index on tie
            float ov = __shfl_xor_sync(0xffffffffu, bestv, o);
            int   oi = __shfl_xor_sync(0xffffffffu, besti, o);
            if (ov > bestv || (ov == bestv && oi < besti)) { bestv = ov; besti = oi; }
        }
        if (tx == 0) out[base + ty * 8 + i] = (float)besti;   // FLOAT output
    }
}

// ---------------------------------------------------------------------------
extern "C" void kernel_launch(void* const* d_in, const int* in_sizes, int n_in,
                              void* d_out, int out_size) {
    const int D = 1024;

    // Runtime input-order disambiguation: h (67.1M elems) vs codebook (0.52M).
    const float* h;
    const float* cb;
    int N;
    if (in_sizes[0] >= in_sizes[1]) {
        h  = (const float*)d_in[0];  N = in_sizes[0] / D;
        cb = (const float*)d_in[1];
    } else {
        h  = (const float*)d_in[1];  N = in_sizes[1] / D;
        cb = (const float*)d_in[0];
    }
    float* out = (float*)d_out;

    encode_kernel<<<N / BM, 256>>>(h, cb, out, N, D);
}